// round 13
// baseline (speedup 1.0000x reference)
#include <cuda_runtime.h>

#define NN 32
#define MM 8
#define PP 16
#define BB 64
#define TT 128
#define NP1 33

// ---------------- global scratch ----------------
__device__ float g_muf[BB][TT][NN];
__device__ float g_mup[BB][TT][NN];
__device__ float g_Sigf[BB][TT][NN][NN];
__device__ float g_Sigp[BB][TT][NN][NN];
__device__ float g_J[BB][TT][NN][NN];    // t in [0, TT-2]
__device__ float g_G[BB][TT][NN][NN];    // Gs_t = Sigf_t - J Sigp_{t+1} J^T
__device__ float g_mb[BB][TT][NN];       // mb_t = muf_t - J mup_{t+1}
__device__ float g_J2[BB][TT][NN][NN];
__device__ float g_G2[BB][TT][NN][NN];
__device__ float g_mb2[BB][TT][NN];
__device__ float g_J4[BB][TT][NN][NN];
__device__ float g_G4[BB][TT][NN][NN];
__device__ float g_mb4[BB][TT][NN];
__device__ float g_Sigs[BB][TT][NN][NN];
__device__ float g_mus[BB][TT][NN];

__device__ __forceinline__ void barh(int half) {
    asm volatile("bar.sync %0, %1;" :: "r"(half + 1), "r"(512) : "memory");
}

// per-half shared state for the forward filter
struct FwdS {
    float sA[NN][NN + 1], sC[PP][NN + 1], sB[NN][MM + 1];
    float sSig[NN][NN + 1], sTmp[NN][NN + 1], sSigp[NN][NN + 1];
    float sH[PP][NN + 1], sCS[PP][NN + 1], sS0[PP][PP + 1], sK[NN][PP + 1];
    float sCA[PP][NN + 1], sCCt[PP][PP + 1];
    float smu[NN], smup[NN], sr[PP], sy[PP], su[MM];
};

// ========== forward filter: 2 batches / CTA, 1024 threads, grid BB/2 ==========
// Each 512-thread half runs R8's proven warp-group-split step on its own batch;
// halves are independent and synchronize only via their own named barrier.
__global__ void __launch_bounds__(1024) fwd_kernel(
    const float* __restrict__ Y, const float* __restrict__ U,
    const float* __restrict__ A, const float* __restrict__ Bm,
    const float* __restrict__ C, const float* __restrict__ mu0,
    const float* __restrict__ Sigma0)
{
    extern __shared__ char smraw[];
    const int half = threadIdx.x >> 9;       // 0 or 1
    const int lt   = threadIdx.x & 511;      // local tid within half
    const int b = blockIdx.x * 2 + half;
    FwdS* S = reinterpret_cast<FwdS*>(smraw) + half;

    const int lane = lt & 31, wid = lt >> 5;
    const int g  = lt >> 8;
    const int t8 = lt & 255;
    const int tx = t8 & 15;
    const int ty = t8 >> 4;

    const float* Ab = A  + (size_t)b * TT * NN * NN;
    const float* Cb = C  + (size_t)b * TT * PP * NN;
    const float* Bb = Bm + (size_t)b * TT * NN * MM;
    const float* Yb = Y  + (size_t)b * TT * PP;
    const float* Ub = U  + (size_t)b * TT * MM;

    for (int idx = lt; idx < NN * NN; idx += 512) {
        S->sSig[idx >> 5][idx & 31] = Sigma0[idx];
        S->sA[idx >> 5][idx & 31]   = Ab[idx];
    }
    for (int idx = lt; idx < PP * NN; idx += 512) S->sC[idx >> 5][idx & 31] = Cb[idx];
    if (lt < NN * MM) S->sB[lt >> 3][lt & 7] = Bb[lt];
    if (lt < NN) S->smu[lt] = mu0[lt];
    if (lt < PP) S->sy[lt] = Yb[lt];
    else if (lt < PP + MM) S->su[lt - PP] = Ub[lt - PP];
    barh(half);

    for (int t = 0; t < TT; ++t) {
        // ==== P1: g0: tmp = A@Sig (2x2) | g1: CA = C@A, CCt = C@C^T | mup ====
        if (g == 0) {
            float a00 = 0.f, a01 = 0.f, a10 = 0.f, a11 = 0.f;
            #pragma unroll
            for (int k = 0; k < NN; ++k) {
                const float l0 = S->sA[ty][k],   l1 = S->sA[ty + 16][k];
                const float r0 = S->sSig[k][tx], r1 = S->sSig[k][tx + 16];
                a00 += l0 * r0; a01 += l0 * r1; a10 += l1 * r0; a11 += l1 * r1;
            }
            S->sTmp[ty][tx] = a00;      S->sTmp[ty][tx + 16] = a01;
            S->sTmp[ty + 16][tx] = a10; S->sTmp[ty + 16][tx + 16] = a11;
        } else {
            float ca0 = 0.f, ca1 = 0.f, cc = 0.f;
            #pragma unroll
            for (int k = 0; k < NN; ++k) {
                const float c = S->sC[ty][k];
                ca0 += c * S->sA[k][tx]; ca1 += c * S->sA[k][tx + 16];
                cc  += c * S->sC[tx][k];
            }
            S->sCA[ty][tx] = ca0; S->sCA[ty][tx + 16] = ca1;
            S->sCCt[ty][tx] = cc;
            if (lt >= 480) {
                const int l = lt - 480;
                float m = 0.f;
                #pragma unroll
                for (int k = 0; k < NN; ++k) m += S->sA[l][k] * S->smu[k];
                #pragma unroll
                for (int k = 0; k < MM; ++k) m += S->sB[l][k] * S->su[k];
                S->smup[l] = m;
            }
        }
        barh(half);

        // ==== P2: g0: Sigp = tmp@A^T + Q | g1: H = C@tmp | r ====
        if (g == 0) {
            float a00 = 0.f, a01 = 0.f, a10 = 0.f, a11 = 0.f;
            #pragma unroll
            for (int k = 0; k < NN; ++k) {
                const float l0 = S->sTmp[ty][k],  l1 = S->sTmp[ty + 16][k];
                const float r0 = S->sA[tx][k],    r1 = S->sA[tx + 16][k];
                a00 += l0 * r0; a01 += l0 * r1; a10 += l1 * r0; a11 += l1 * r1;
            }
            const float q = (ty == tx) ? 0.01f : 0.f;
            a00 += q; a11 += q;
            S->sSigp[ty][tx] = a00;      S->sSigp[ty][tx + 16] = a01;
            S->sSigp[ty + 16][tx] = a10; S->sSigp[ty + 16][tx + 16] = a11;
            float* gp = &g_Sigp[b][t][0][0];
            gp[ty * NN + tx] = a00;        gp[ty * NN + tx + 16] = a01;
            gp[(ty + 16) * NN + tx] = a10; gp[(ty + 16) * NN + tx + 16] = a11;
        } else {
            float h0 = 0.f, h1 = 0.f;
            #pragma unroll
            for (int k = 0; k < NN; ++k) {
                const float c = S->sC[ty][k];
                h0 += c * S->sTmp[k][tx]; h1 += c * S->sTmp[k][tx + 16];
            }
            S->sH[ty][tx] = h0; S->sH[ty][tx + 16] = h1;
            if (lt >= 480 && lt < 480 + PP) {
                const int i = lt - 480;
                float m = 0.f;
                #pragma unroll
                for (int k = 0; k < NN; ++k) m += S->sC[i][k] * S->smup[k];
                S->sr[i] = S->sy[i] - m;
            }
        }
        barh(half);

        // ==== P3: g0: CS = H@A^T + 0.01C | g1: S0 = H@CA^T + 0.01 CCt ====
        if (g == 0) {
            float cs0 = 0.f, cs1 = 0.f;
            #pragma unroll
            for (int k = 0; k < NN; ++k) {
                const float h = S->sH[ty][k];
                cs0 += h * S->sA[tx][k]; cs1 += h * S->sA[tx + 16][k];
            }
            S->sCS[ty][tx]      = cs0 + 0.01f * S->sC[ty][tx];
            S->sCS[ty][tx + 16] = cs1 + 0.01f * S->sC[ty][tx + 16];
        } else {
            float s0 = 0.f;
            #pragma unroll
            for (int k = 0; k < NN; ++k) s0 += S->sH[ty][k] * S->sCA[tx][k];
            S->sS0[ty][tx] = s0 + 0.01f * S->sCCt[ty][tx];
        }
        barh(half);

        // ==== P4: warp0 GJ on [sym(S0)+R | CS] -> K ; warps 1-15 prefetch ====
        if (wid == 0) {
            float colA[PP], colB[PP];
            #pragma unroll
            for (int i = 0; i < PP; ++i) {
                colA[i] = (lane < PP)
                    ? 0.5f * (S->sS0[i][lane] + S->sS0[lane][i]) + ((i == lane) ? 0.01f : 0.f)
                    : S->sCS[i][lane - PP];
                colB[i] = (lane < PP) ? S->sCS[i][PP + lane] : 0.f;
            }
            #pragma unroll
            for (int k = 0; k < PP; ++k) {
                float f[PP];
                #pragma unroll
                for (int i = 0; i < PP; ++i) f[i] = __shfl_sync(0xffffffffu, colA[i], k);
                const float pr = 1.0f / f[k];
                #pragma unroll
                for (int i = 0; i < PP; ++i) {
                    if (i != k) {
                        const float gg = f[i] * pr;
                        colA[i] -= gg * colA[k];
                        colB[i] -= gg * colB[k];
                    }
                }
                colA[k] *= pr; colB[k] *= pr;
            }
            if (lane >= PP) {
                #pragma unroll
                for (int i = 0; i < PP; ++i) S->sK[lane - PP][i] = colA[i];
            } else {
                #pragma unroll
                for (int i = 0; i < PP; ++i) S->sK[PP + lane][i] = colB[i];
            }
        } else if (t + 1 < TT) {
            const int wt = lt - 32;
            const float* An = Ab + (size_t)(t + 1) * NN * NN;
            const float* Cn = Cb + (size_t)(t + 1) * PP * NN;
            const float* Bn = Bb + (size_t)(t + 1) * NN * MM;
            for (int idx = wt; idx < NN * NN; idx += 480) S->sA[idx >> 5][idx & 31] = An[idx];
            for (int idx = wt; idx < PP * NN; idx += 480) S->sC[idx >> 5][idx & 31] = Cn[idx];
            for (int idx = wt; idx < NN * MM; idx += 480) S->sB[idx >> 3][idx & 7] = Bn[idx];
            if (wt < PP) S->sy[wt] = Yb[(t + 1) * PP + wt];
            else if (wt < PP + MM) S->su[wt - PP] = Ub[(t + 1) * MM + (wt - PP)];
        }
        barh(half);

        // ==== P5: Sig_f = Sigp - K@CS (algebraically symmetric); mu_f ====
        {
            const int i0 = wid, j = lane;
            float x0 = S->sSigp[i0][j], x1 = S->sSigp[i0 + 16][j];
            #pragma unroll
            for (int k = 0; k < PP; ++k) {
                const float c = S->sCS[k][j];
                x0 -= S->sK[i0][k] * c; x1 -= S->sK[i0 + 16][k] * c;
            }
            S->sSig[i0][j] = x0; S->sSig[i0 + 16][j] = x1;
            float* gf = &g_Sigf[b][t][0][0];
            gf[i0 * NN + j] = x0; gf[(i0 + 16) * NN + j] = x1;
        }
        if (lt < NN) {
            float m = S->smup[lt];
            #pragma unroll
            for (int k = 0; k < PP; ++k) m += S->sK[lt][k] * S->sr[k];
            S->smu[lt] = m;
            g_muf[b][t][lt] = m;
            g_mup[b][t][lt] = S->smup[lt];
        }
        barh(half);
    }
}

// ===== smoother gains + backward constants (fully parallel over b,t) =====
__global__ void __launch_bounds__(256) jgain_kernel(const float* __restrict__ A)
{
    const int t = blockIdx.x;     // 0..TT-2
    const int b = blockIdx.y;
    const int tid = threadIdx.x;
    const int tx = tid & 15, ty = tid >> 4;

    __shared__ float sSf[NN][NN + 1], sA[NN][NN + 1], sX[NN][NN + 1], sT2[NN][NN + 1];
    __shared__ float prow[2][2 * NN];
    __shared__ float sf[2][NN];
    __shared__ float smp1[NN];

    const float* Ab = A + ((size_t)b * TT + t) * NN * NN;
    for (int idx = tid; idx < NN * NN; idx += 256) {
        sSf[idx >> 5][idx & 31] = g_Sigf[b][t][idx >> 5][idx & 31];
        sA[idx >> 5][idx & 31]  = Ab[idx];
    }
    if (tid < NN) smp1[tid] = g_mup[b][t + 1][tid];
    __syncthreads();

    // X = Sigf @ A^T
    {
        float a00 = 0.f, a01 = 0.f, a10 = 0.f, a11 = 0.f;
        #pragma unroll
        for (int k = 0; k < NN; ++k) {
            const float l0 = sSf[ty][k], l1 = sSf[ty + 16][k];
            const float r0 = sA[tx][k],  r1 = sA[tx + 16][k];
            a00 += l0 * r0; a01 += l0 * r1; a10 += l1 * r0; a11 += l1 * r1;
        }
        sX[ty][tx] = a00;      sX[ty][tx + 16] = a01;
        sX[ty + 16][tx] = a10; sX[ty + 16][tx + 16] = a11;
    }
    __syncthreads();

    // Gauss-Jordan on [Sigp_{t+1} | X^T]
    const int row = tid >> 3;
    const int c0  = (tid & 7) * 8;
    float r8[8];
    if (c0 < NN) {
        #pragma unroll
        for (int m = 0; m < 8; ++m) r8[m] = g_Sigp[b][t + 1][row][c0 + m];
    } else {
        #pragma unroll
        for (int m = 0; m < 8; ++m) r8[m] = sX[c0 - NN + m][row];   // X^T
    }
    #pragma unroll
    for (int k = 0; k < NN; ++k) {
        const int pb = k & 1;
        if (row == k) {
            #pragma unroll
            for (int m = 0; m < 8; ++m) prow[pb][c0 + m] = r8[m];
        }
        if ((tid & 7) == (k >> 3)) sf[pb][row] = r8[k & 7];
        __syncthreads();
        const float pr = 1.0f / prow[pb][k];
        if (row == k) {
            #pragma unroll
            for (int m = 0; m < 8; ++m) r8[m] *= pr;
        } else {
            const float g = sf[pb][row] * pr;
            #pragma unroll
            for (int m = 0; m < 8; ++m) r8[m] -= g * prow[pb][c0 + m];
        }
    }
    __syncthreads();
    if (c0 >= NN) {
        #pragma unroll
        for (int m = 0; m < 8; ++m) sX[c0 - NN + m][row] = r8[m];   // J
    }
    __syncthreads();
    for (int idx = tid; idx < NN * NN; idx += 256) {
        g_J[b][t][idx >> 5][idx & 31] = sX[idx >> 5][idx & 31];
        sA[idx >> 5][idx & 31] = g_Sigp[b][t + 1][idx >> 5][idx & 31];
    }
    __syncthreads();

    // T2 = J @ Sigp_{t+1}
    {
        float a00 = 0.f, a01 = 0.f, a10 = 0.f, a11 = 0.f;
        #pragma unroll
        for (int k = 0; k < NN; ++k) {
            const float l0 = sX[ty][k], l1 = sX[ty + 16][k];
            const float r0 = sA[k][tx], r1 = sA[k][tx + 16];
            a00 += l0 * r0; a01 += l0 * r1; a10 += l1 * r0; a11 += l1 * r1;
        }
        sT2[ty][tx] = a00;      sT2[ty][tx + 16] = a01;
        sT2[ty + 16][tx] = a10; sT2[ty + 16][tx + 16] = a11;
    }
    __syncthreads();

    // G = Sf - T2 @ J^T ; mb = muf - J mp1
    {
        float e00 = 0.f, e01 = 0.f, e10 = 0.f, e11 = 0.f;
        #pragma unroll
        for (int k = 0; k < NN; ++k) {
            const float t0 = sT2[ty][k], t1 = sT2[ty + 16][k];
            const float j0 = sX[tx][k],  j1 = sX[tx + 16][k];
            e00 += t0 * j0; e01 += t0 * j1; e10 += t1 * j0; e11 += t1 * j1;
        }
        float* gg = &g_G[b][t][0][0];
        gg[ty * NN + tx]             = sSf[ty][tx]           - e00;
        gg[ty * NN + tx + 16]        = sSf[ty][tx + 16]      - e01;
        gg[(ty + 16) * NN + tx]      = sSf[ty + 16][tx]      - e10;
        gg[(ty + 16) * NN + tx + 16] = sSf[ty + 16][tx + 16] - e11;
    }
    if (tid < NN) {
        float m = g_muf[b][t][tid];
        #pragma unroll
        for (int k = 0; k < NN; ++k) m -= sX[tid][k] * smp1[k];
        g_mb[b][t][tid] = m;
    }
}

// ===== pair2: stride-2 composites at odd t =====
__global__ void __launch_bounds__(256) pair2_kernel()
{
    const int t = 2 * blockIdx.x + 1;
    const int b = blockIdx.y;
    const int tid = threadIdx.x;
    const int tx = tid & 15, ty = tid >> 4;

    __shared__ float sJ[NN][NN + 1], sJn[NN][NN + 1], sGn[NN][NN + 1], sT[NN][NN + 1];
    __shared__ float smbn[NN];

    for (int idx = tid; idx < NN * NN; idx += 256) {
        const int i = idx >> 5, j = idx & 31;
        sJ[i][j]  = g_J[b][t][i][j];
        sJn[i][j] = g_J[b][t + 1][i][j];
        sGn[i][j] = g_G[b][t + 1][i][j];
    }
    if (tid < NN) smbn[tid] = g_mb[b][t + 1][tid];
    __syncthreads();

    {
        float a00 = 0.f, a01 = 0.f, a10 = 0.f, a11 = 0.f;
        float b00 = 0.f, b01 = 0.f, b10 = 0.f, b11 = 0.f;
        #pragma unroll
        for (int k = 0; k < NN; ++k) {
            const float l0 = sJ[ty][k], l1 = sJ[ty + 16][k];
            const float r0 = sJn[k][tx], r1 = sJn[k][tx + 16];
            const float g0 = sGn[k][tx], g1 = sGn[k][tx + 16];
            a00 += l0 * r0; a01 += l0 * r1; a10 += l1 * r0; a11 += l1 * r1;
            b00 += l0 * g0; b01 += l0 * g1; b10 += l1 * g0; b11 += l1 * g1;
        }
        float* j2 = &g_J2[b][t][0][0];
        j2[ty * NN + tx] = a00;        j2[ty * NN + tx + 16] = a01;
        j2[(ty + 16) * NN + tx] = a10; j2[(ty + 16) * NN + tx + 16] = a11;
        sT[ty][tx] = b00;      sT[ty][tx + 16] = b01;
        sT[ty + 16][tx] = b10; sT[ty + 16][tx + 16] = b11;
    }
    if (tid < NN) {
        float m = g_mb[b][t][tid];
        #pragma unroll
        for (int k = 0; k < NN; ++k) m += sJ[tid][k] * smbn[k];
        g_mb2[b][t][tid] = m;
    }
    __syncthreads();

    {
        float e00 = 0.f, e01 = 0.f, e10 = 0.f, e11 = 0.f;
        #pragma unroll
        for (int k = 0; k < NN; ++k) {
            const float t0 = sT[ty][k], t1 = sT[ty + 16][k];
            const float j0 = sJ[tx][k], j1 = sJ[tx + 16][k];
            e00 += t0 * j0; e01 += t0 * j1; e10 += t1 * j0; e11 += t1 * j1;
        }
        float* g2 = &g_G2[b][t][0][0];
        g2[ty * NN + tx]             = g_G[b][t][ty][tx]           + e00;
        g2[ty * NN + tx + 16]        = g_G[b][t][ty][tx + 16]      + e01;
        g2[(ty + 16) * NN + tx]      = g_G[b][t][ty + 16][tx]      + e10;
        g2[(ty + 16) * NN + tx + 16] = g_G[b][t][ty + 16][tx + 16] + e11;
    }
}

// ===== pair4: stride-4 composites =====
__global__ void __launch_bounds__(256) pair4_kernel()
{
    const int t = 4 * blockIdx.x + 3;
    const int b = blockIdx.y;
    const int tid = threadIdx.x;
    const int tx = tid & 15, ty = tid >> 4;

    __shared__ float sJ[NN][NN + 1], sJn[NN][NN + 1], sGn[NN][NN + 1], sT[NN][NN + 1];
    __shared__ float smbn[NN];

    for (int idx = tid; idx < NN * NN; idx += 256) {
        const int i = idx >> 5, j = idx & 31;
        sJ[i][j]  = g_J2[b][t][i][j];
        sJn[i][j] = g_J2[b][t + 2][i][j];
        sGn[i][j] = g_G2[b][t + 2][i][j];
    }
    if (tid < NN) smbn[tid] = g_mb2[b][t + 2][tid];
    __syncthreads();

    {
        float a00 = 0.f, a01 = 0.f, a10 = 0.f, a11 = 0.f;
        float b00 = 0.f, b01 = 0.f, b10 = 0.f, b11 = 0.f;
        #pragma unroll
        for (int k = 0; k < NN; ++k) {
            const float l0 = sJ[ty][k], l1 = sJ[ty + 16][k];
            const float r0 = sJn[k][tx], r1 = sJn[k][tx + 16];
            const float g0 = sGn[k][tx], g1 = sGn[k][tx + 16];
            a00 += l0 * r0; a01 += l0 * r1; a10 += l1 * r0; a11 += l1 * r1;
            b00 += l0 * g0; b01 += l0 * g1; b10 += l1 * g0; b11 += l1 * g1;
        }
        float* j4 = &g_J4[b][t][0][0];
        j4[ty * NN + tx] = a00;        j4[ty * NN + tx + 16] = a01;
        j4[(ty + 16) * NN + tx] = a10; j4[(ty + 16) * NN + tx + 16] = a11;
        sT[ty][tx] = b00;      sT[ty][tx + 16] = b01;
        sT[ty + 16][tx] = b10; sT[ty + 16][tx + 16] = b11;
    }
    if (tid < NN) {
        float m = g_mb2[b][t][tid];
        #pragma unroll
        for (int k = 0; k < NN; ++k) m += sJ[tid][k] * smbn[k];
        g_mb4[b][t][tid] = m;
    }
    __syncthreads();

    {
        float e00 = 0.f, e01 = 0.f, e10 = 0.f, e11 = 0.f;
        #pragma unroll
        for (int k = 0; k < NN; ++k) {
            const float t0 = sT[ty][k], t1 = sT[ty + 16][k];
            const float j0 = sJ[tx][k], j1 = sJ[tx + 16][k];
            e00 += t0 * j0; e01 += t0 * j1; e10 += t1 * j0; e11 += t1 * j1;
        }
        float* g4 = &g_G4[b][t][0][0];
        g4[ty * NN + tx]             = g_G2[b][t][ty][tx]           + e00;
        g4[ty * NN + tx + 16]        = g_G2[b][t][ty][tx + 16]      + e01;
        g4[(ty + 16) * NN + tx]      = g_G2[b][t][ty + 16][tx]      + e10;
        g4[(ty + 16) * NN + tx + 16] = g_G2[b][t][ty + 16][tx + 16] + e11;
    }
}

// ===== serial backward (stride-4, 31 steps): 2 batches / CTA, 1024 threads =====
__global__ void __launch_bounds__(1024) bwd4_kernel(float* __restrict__ out)
{
    const int half = threadIdx.x >> 9;
    const int lt   = threadIdx.x & 511;
    const int b = blockIdx.x * 2 + half;
    const int j  = lt & 31;
    const int i0 = lt >> 5;

    __shared__ float sJ[2][2][NN][NN + 1], sTmp[2][NN][NN + 1], sSig[2][NN][NN + 1];
    __shared__ float smu[2][NN];

    {
        const float v0 = g_Sigf[b][TT - 1][i0][j];
        const float v1 = g_Sigf[b][TT - 1][i0 + 16][j];
        sSig[half][i0][j] = v0; sSig[half][i0 + 16][j] = v1;
        g_Sigs[b][TT - 1][i0][j] = v0; g_Sigs[b][TT - 1][i0 + 16][j] = v1;
        const size_t base = ((size_t)b * TT + (TT - 1)) * NN;
        out[(base + i0) * NP1 + 1 + j] = v0;
        out[(base + i0 + 16) * NP1 + 1 + j] = v1;
        if (lt < NN) {
            const float m = g_muf[b][TT - 1][lt];
            smu[half][lt] = m;
            g_mus[b][TT - 1][lt] = m;
            out[(base + lt) * NP1] = m;
        }
    }
    float pG0 = g_G4[b][123][i0][j];
    float pG1 = g_G4[b][123][i0 + 16][j];
    sJ[half][0][i0][j]      = g_J4[b][123][i0][j];
    sJ[half][0][i0 + 16][j] = g_J4[b][123][i0 + 16][j];
    barh(half);

    int cur = 0;
    for (int v = 30; v >= 0; --v) {
        const int t = 4 * v + 3;
        float a0 = 0.f, a1 = 0.f;
        #pragma unroll
        for (int k = 0; k < NN; ++k) {
            const float r = sSig[half][k][j];
            a0 += sJ[half][cur][i0][k] * r; a1 += sJ[half][cur][i0 + 16][k] * r;
        }
        sTmp[half][i0][j] = a0; sTmp[half][i0 + 16][j] = a1;

        float m = 0.f;
        if (lt < NN) {
            m = g_mb4[b][t][lt];
            #pragma unroll
            for (int k = 0; k < NN; ++k) m += sJ[half][cur][lt][k] * smu[half][k];
        }
        float nJ0 = 0.f, nJ1 = 0.f, nG0 = 0.f, nG1 = 0.f;
        if (v > 0) {
            nJ0 = g_J4[b][t - 4][i0][j];     nJ1 = g_J4[b][t - 4][i0 + 16][j];
            nG0 = g_G4[b][t - 4][i0][j];     nG1 = g_G4[b][t - 4][i0 + 16][j];
        }
        barh(half);

        {
            float e0 = 0.f, e1 = 0.f;
            #pragma unroll
            for (int k = 0; k < NN; ++k) {
                const float jj = sJ[half][cur][j][k];
                e0 += sTmp[half][i0][k] * jj; e1 += sTmp[half][i0 + 16][k] * jj;
            }
            const float v0 = pG0 + e0;
            const float v1 = pG1 + e1;
            sSig[half][i0][j] = v0; sSig[half][i0 + 16][j] = v1;
            g_Sigs[b][t][i0][j] = v0; g_Sigs[b][t][i0 + 16][j] = v1;
            const size_t base = ((size_t)b * TT + t) * NN;
            out[(base + i0) * NP1 + 1 + j] = v0;
            out[(base + i0 + 16) * NP1 + 1 + j] = v1;
            if (lt < NN) {
                smu[half][lt] = m;
                g_mus[b][t][lt] = m;
                out[(base + lt) * NP1] = m;
            }
        }
        if (v > 0) {
            sJ[half][cur ^ 1][i0][j] = nJ0; sJ[half][cur ^ 1][i0 + 16][j] = nJ1;
            pG0 = nG0; pG1 = nG1;
        }
        barh(half);
        cur ^= 1;
    }
}

// ===== fillA: t = 4w+1 via stride-2 ops =====
__global__ void __launch_bounds__(256) fillA_kernel(float* __restrict__ out)
{
    const int t = 4 * blockIdx.x + 1;
    const int b = blockIdx.y;
    const int tid = threadIdx.x;
    const int tx = tid & 15, ty = tid >> 4;

    __shared__ float sJ[NN][NN + 1], sS[NN][NN + 1], sT[NN][NN + 1];
    __shared__ float smun[NN];

    for (int idx = tid; idx < NN * NN; idx += 256) {
        const int i = idx >> 5, j = idx & 31;
        sJ[i][j] = g_J2[b][t][i][j];
        sS[i][j] = g_Sigs[b][t + 2][i][j];
    }
    if (tid < NN) smun[tid] = g_mus[b][t + 2][tid];
    __syncthreads();

    {
        float a00 = 0.f, a01 = 0.f, a10 = 0.f, a11 = 0.f;
        #pragma unroll
        for (int k = 0; k < NN; ++k) {
            const float l0 = sJ[ty][k], l1 = sJ[ty + 16][k];
            const float r0 = sS[k][tx], r1 = sS[k][tx + 16];
            a00 += l0 * r0; a01 += l0 * r1; a10 += l1 * r0; a11 += l1 * r1;
        }
        sT[ty][tx] = a00;      sT[ty][tx + 16] = a01;
        sT[ty + 16][tx] = a10; sT[ty + 16][tx + 16] = a11;
    }
    __syncthreads();
    {
        float e00 = 0.f, e01 = 0.f, e10 = 0.f, e11 = 0.f;
        #pragma unroll
        for (int k = 0; k < NN; ++k) {
            const float t0 = sT[ty][k], t1 = sT[ty + 16][k];
            const float j0 = sJ[tx][k], j1 = sJ[tx + 16][k];
            e00 += t0 * j0; e01 += t0 * j1; e10 += t1 * j0; e11 += t1 * j1;
        }
        const float v00 = g_G2[b][t][ty][tx]           + e00;
        const float v01 = g_G2[b][t][ty][tx + 16]      + e01;
        const float v10 = g_G2[b][t][ty + 16][tx]      + e10;
        const float v11 = g_G2[b][t][ty + 16][tx + 16] + e11;
        g_Sigs[b][t][ty][tx] = v00;        g_Sigs[b][t][ty][tx + 16] = v01;
        g_Sigs[b][t][ty + 16][tx] = v10;   g_Sigs[b][t][ty + 16][tx + 16] = v11;
        const size_t base = ((size_t)b * TT + t) * NN;
        out[(base + ty) * NP1 + 1 + tx]           = v00;
        out[(base + ty) * NP1 + 1 + tx + 16]      = v01;
        out[(base + ty + 16) * NP1 + 1 + tx]      = v10;
        out[(base + ty + 16) * NP1 + 1 + tx + 16] = v11;
    }
    if (tid < NN) {
        float m = g_mb2[b][t][tid];
        #pragma unroll
        for (int k = 0; k < NN; ++k) m += sJ[tid][k] * smun[k];
        g_mus[b][t][tid] = m;
        out[(((size_t)b * TT + t) * NN + tid) * NP1] = m;
    }
}

// ===== fillB: even t via stride-1 ops =====
__global__ void __launch_bounds__(256) fillB_kernel(float* __restrict__ out)
{
    const int t = 2 * blockIdx.x;
    const int b = blockIdx.y;
    const int tid = threadIdx.x;
    const int tx = tid & 15, ty = tid >> 4;

    __shared__ float sJ[NN][NN + 1], sS[NN][NN + 1], sT[NN][NN + 1];
    __shared__ float smun[NN];

    for (int idx = tid; idx < NN * NN; idx += 256) {
        const int i = idx >> 5, j = idx & 31;
        sJ[i][j] = g_J[b][t][i][j];
        sS[i][j] = g_Sigs[b][t + 1][i][j];
    }
    if (tid < NN) smun[tid] = g_mus[b][t + 1][tid];
    __syncthreads();

    {
        float a00 = 0.f, a01 = 0.f, a10 = 0.f, a11 = 0.f;
        #pragma unroll
        for (int k = 0; k < NN; ++k) {
            const float l0 = sJ[ty][k], l1 = sJ[ty + 16][k];
            const float r0 = sS[k][tx], r1 = sS[k][tx + 16];
            a00 += l0 * r0; a01 += l0 * r1; a10 += l1 * r0; a11 += l1 * r1;
        }
        sT[ty][tx] = a00;      sT[ty][tx + 16] = a01;
        sT[ty + 16][tx] = a10; sT[ty + 16][tx + 16] = a11;
    }
    __syncthreads();
    {
        float e00 = 0.f, e01 = 0.f, e10 = 0.f, e11 = 0.f;
        #pragma unroll
        for (int k = 0; k < NN; ++k) {
            const float t0 = sT[ty][k], t1 = sT[ty + 16][k];
            const float j0 = sJ[tx][k], j1 = sJ[tx + 16][k];
            e00 += t0 * j0; e01 += t0 * j1; e10 += t1 * j0; e11 += t1 * j1;
        }
        const size_t base = ((size_t)b * TT + t) * NN;
        out[(base + ty) * NP1 + 1 + tx]           = g_G[b][t][ty][tx]           + e00;
        out[(base + ty) * NP1 + 1 + tx + 16]      = g_G[b][t][ty][tx + 16]      + e01;
        out[(base + ty + 16) * NP1 + 1 + tx]      = g_G[b][t][ty + 16][tx]      + e10;
        out[(base + ty + 16) * NP1 + 1 + tx + 16] = g_G[b][t][ty + 16][tx + 16] + e11;
    }
    if (tid < NN) {
        float m = g_mb[b][t][tid];
        #pragma unroll
        for (int k = 0; k < NN; ++k) m += sJ[tid][k] * smun[k];
        out[(((size_t)b * TT + t) * NN + tid) * NP1] = m;
    }
}

// ---------------- launch ----------------
extern "C" void kernel_launch(void* const* d_in, const int* in_sizes, int n_in,
                              void* d_out, int out_size)
{
    const float* Y      = (const float*)d_in[0];
    const float* U      = (const float*)d_in[1];
    const float* A      = (const float*)d_in[2];
    const float* Bm     = (const float*)d_in[3];
    const float* C      = (const float*)d_in[4];
    const float* mu0    = (const float*)d_in[5];
    const float* Sigma0 = (const float*)d_in[6];
    float* out = (float*)d_out;

    const int fwd_smem = (int)(2 * sizeof(FwdS));
    cudaFuncSetAttribute(fwd_kernel, cudaFuncAttributeMaxDynamicSharedMemorySize, fwd_smem);

    fwd_kernel<<<BB / 2, 1024, fwd_smem>>>(Y, U, A, Bm, C, mu0, Sigma0);
    jgain_kernel<<<dim3(TT - 1, BB), 256>>>(A);
    pair2_kernel<<<dim3(63, BB), 256>>>();
    pair4_kernel<<<dim3(31, BB), 256>>>();
    bwd4_kernel<<<BB / 2, 1024>>>(out);
    fillA_kernel<<<dim3(32, BB), 256>>>(out);
    fillB_kernel<<<dim3(64, BB), 256>>>(out);
}